// round 11
// baseline (speedup 1.0000x reference)
#include <cuda_runtime.h>
#include <cuda_bf16.h>

// MeanSquaredError2: loss = [ sum(h^2) + sum_{vis}(1 - 2*h[b,j,xi,yi]) ] * 2/size
// o input unused. Single-kernel HBM-bound streaming reduction.
// = thrice-validated best config (31.2us), with the one unprobed knob:
// 512-thread blocks (same 64 warps/SM, half the CTAs -> half the finalize
// atomics and block-reduce instances on the tail).

#define COLS 14
#define CELLS (COLS * COLS)   // 196
#define THREADS 512

__device__ float         g_partial = 0.0f;
__device__ unsigned int  g_arrived = 0u;

__global__ __launch_bounds__(THREADS) void mse_reduce_kernel(
    const float4* __restrict__ h4, long long n4,
    const float*  __restrict__ h,
    const float*  __restrict__ t,
    const int*    __restrict__ v,
    int npairs, float scale, float* __restrict__ out)
{
    const int tid  = threadIdx.x;
    const long long gid = (long long)blockIdx.x * THREADS + tid;
    const long long gstride = (long long)gridDim.x * THREADS;

    float local = 0.0f;

    // Main streaming pass: one coalesced LDG.128 per iteration (evict-first).
    for (long long i = gid; i < n4; i += gstride) {
        float4 x = __ldcs(&h4[i]);
        local += x.x * x.x + x.y * x.y + x.z * x.z + x.w * x.w;
    }

    // One-hot correction: one (b,j) pair per global thread.
    if (gid < npairs) {
        int p = (int)gid;
        if (__ldg(&v[p]) == 1) {
            float tx = __ldg(&t[2 * p]);
            float ty = __ldg(&t[2 * p + 1]);
            int xi = (int)(tx * (float)COLS);
            int yi = (int)(ty * (float)COLS);
            xi = min(max(xi, 0), COLS - 1);
            yi = min(max(yi, 0), COLS - 1);
            float hv = __ldg(&h[(long long)p * CELLS + xi * COLS + yi]);
            local += 1.0f - 2.0f * hv;
        }
    }

    // Warp reduce
    #pragma unroll
    for (int off = 16; off > 0; off >>= 1)
        local += __shfl_xor_sync(0xFFFFFFFFu, local, off);

    // Block reduce via shared
    __shared__ float warp_sums[THREADS / 32];
    int lane = tid & 31, wid = tid >> 5;
    if (lane == 0) warp_sums[wid] = local;
    __syncthreads();
    if (wid == 0) {
        local = (lane < (THREADS >> 5)) ? warp_sums[lane] : 0.0f;
        #pragma unroll
        for (int off = 8; off > 0; off >>= 1)
            local += __shfl_xor_sync(0xFFFFFFFFu, local, off);
        if (lane == 0) {
            atomicAdd(&g_partial, local);
            __threadfence();
            unsigned int prev = atomicAdd(&g_arrived, 1u);
            if (prev == gridDim.x - 1) {
                // Last block: publish result, reset scratch for next replay.
                float total = atomicAdd(&g_partial, 0.0f);  // ordered read
                out[0] = total * scale;
                g_partial = 0.0f;
                __threadfence();
                g_arrived = 0u;
            }
        }
    }
}

extern "C" void kernel_launch(void* const* d_in, const int* in_sizes, int n_in,
                              void* d_out, int out_size)
{
    // Inputs (metadata order): o (unused), h, t, v
    const float* h = (const float*)d_in[1];
    const float* t = (const float*)d_in[2];
    const int*   v = (const int*)d_in[3];
    float* out = (float*)d_out;

    long long hsize = (long long)in_sizes[1];       // B*NJ*14*14
    long long n4 = hsize / 4;                       // divisible
    int npairs = in_sizes[3];                       // B*NJ
    float scale = 2.0f / (float)hsize;              // 1 / (size/2)

    int blocks = 592;                               // 148 SMs * 4 blocks (64 warps/SM)
    long long total = (long long)blocks * THREADS;
    if (total < npairs) blocks = (npairs + THREADS - 1) / THREADS;

    mse_reduce_kernel<<<blocks, THREADS>>>(
        (const float4*)h, n4, h, t, v, npairs, scale, out);
}

// round 16
// speedup vs baseline: 1.0543x; 1.0543x over previous
#include <cuda_runtime.h>
#include <cuda_bf16.h>

// MeanSquaredError2: loss = [ sum(h^2) + sum_{vis}(1 - 2*h[b,j,xi,yi]) ] * 2/size
// o input unused. Single-kernel HBM-bound streaming reduction.
// FINAL CONFIG — measured 31.5/31.2/31.2us across three independent benches:
//  - plain grid-stride, one LDG.128 (__ldcs, read-once evict-first) per iter
//    (explicit unrolls at MLP_p1>=2 regressed 2-4us: cross-CTA L1tex queue
//    contention per B300 spread model; 64 warps/SM already saturate MLP)
//  - scattered one-hot correction AFTER the stream (before-stream cost 1.8us)
//  - fused last-block finalize via device scratch (removes init launch, 1.6us)
//  - 256-thread blocks, 1184 CTAs = one full wave at occ 8
// Remaining variants (ldg policy, split prefetch, 512-thread blocks) all
// landed inside the +/-1us noise band; 180MB read of h is irreducible.
// (R12 submission of this exact source hit a broker infra failure; resubmit.)

#define COLS 14
#define CELLS (COLS * COLS)   // 196
#define THREADS 256

__device__ float         g_partial = 0.0f;
__device__ unsigned int  g_arrived = 0u;

__global__ __launch_bounds__(THREADS) void mse_reduce_kernel(
    const float4* __restrict__ h4, long long n4,
    const float*  __restrict__ h,
    const float*  __restrict__ t,
    const int*    __restrict__ v,
    int npairs, float scale, float* __restrict__ out)
{
    const int tid  = threadIdx.x;
    const long long gid = (long long)blockIdx.x * THREADS + tid;
    const long long gstride = (long long)gridDim.x * THREADS;

    float local = 0.0f;

    // Main streaming pass: one coalesced LDG.128 per iteration (evict-first).
    for (long long i = gid; i < n4; i += gstride) {
        float4 x = __ldcs(&h4[i]);
        local += x.x * x.x + x.y * x.y + x.z * x.z + x.w * x.w;
    }

    // One-hot correction: one (b,j) pair per global thread.
    if (gid < npairs) {
        int p = (int)gid;
        if (__ldg(&v[p]) == 1) {
            float tx = __ldg(&t[2 * p]);
            float ty = __ldg(&t[2 * p + 1]);
            int xi = (int)(tx * (float)COLS);
            int yi = (int)(ty * (float)COLS);
            xi = min(max(xi, 0), COLS - 1);
            yi = min(max(yi, 0), COLS - 1);
            float hv = __ldg(&h[(long long)p * CELLS + xi * COLS + yi]);
            local += 1.0f - 2.0f * hv;
        }
    }

    // Warp reduce
    #pragma unroll
    for (int off = 16; off > 0; off >>= 1)
        local += __shfl_xor_sync(0xFFFFFFFFu, local, off);

    // Block reduce via shared
    __shared__ float warp_sums[THREADS / 32];
    int lane = tid & 31, wid = tid >> 5;
    if (lane == 0) warp_sums[wid] = local;
    __syncthreads();
    if (wid == 0) {
        local = (lane < (THREADS >> 5)) ? warp_sums[lane] : 0.0f;
        #pragma unroll
        for (int off = 4; off > 0; off >>= 1)
            local += __shfl_xor_sync(0xFFFFFFFFu, local, off);
        if (lane == 0) {
            atomicAdd(&g_partial, local);
            __threadfence();
            unsigned int prev = atomicAdd(&g_arrived, 1u);
            if (prev == gridDim.x - 1) {
                // Last block: publish result, reset scratch for next replay.
                float total = atomicAdd(&g_partial, 0.0f);  // ordered read
                out[0] = total * scale;
                g_partial = 0.0f;
                __threadfence();
                g_arrived = 0u;
            }
        }
    }
}

extern "C" void kernel_launch(void* const* d_in, const int* in_sizes, int n_in,
                              void* d_out, int out_size)
{
    // Inputs (metadata order): o (unused), h, t, v
    const float* h = (const float*)d_in[1];
    const float* t = (const float*)d_in[2];
    const int*   v = (const int*)d_in[3];
    float* out = (float*)d_out;

    long long hsize = (long long)in_sizes[1];       // B*NJ*14*14
    long long n4 = hsize / 4;                       // divisible
    int npairs = in_sizes[3];                       // B*NJ
    float scale = 2.0f / (float)hsize;              // 1 / (size/2)

    int blocks = 1184;                              // 148 SMs * 8 blocks, one wave
    long long total = (long long)blocks * THREADS;
    if (total < npairs) blocks = (npairs + THREADS - 1) / THREADS;

    mse_reduce_kernel<<<blocks, THREADS>>>(
        (const float4*)h, n4, h, t, v, npairs, scale, out);
}